// round 8
// baseline (speedup 1.0000x reference)
#include <cuda_runtime.h>
#include <math.h>
#include <stdint.h>

#define NN 4096
#define DD 128
#define EPSF 1e-12f
#define SPLITK 8
#define KCHUNK (NN / SPLITK)   // 512
#define BM 128
#define BK 32
#define NIT (KCHUNK / BK)      // 16
#define SA 132
#define SB 132

// ---------------- device scratch (no allocations allowed) ----------------
__device__ float g_feat[NN * DD];               // W @ activities
__device__ float g_part[SPLITK][NN * DD];       // split-K partials, 16 MB
__device__ float g_val[1 << 20];                // per-edge exp(-dist)
__device__ int   g_cnt[NN];                     // edges per target
__device__ int   g_off[NN];                     // exclusive prefix
__device__ int   g_cur[NN];                     // scatter cursors
__device__ int   g_eid[1 << 20];                // permuted edge ids
__device__ int   g_ec[1 << 20];                 // permuted current ids
__device__ int   g_idx64;                       // 1 if indices are int64

// ---------------- streams/events for graph fork-join (no device mem) ------
struct HXStreams {
    cudaStream_t s1, s2;
    cudaEvent_t root, done1, done2;
    HXStreams() {
        cudaStreamCreateWithFlags(&s1, cudaStreamNonBlocking);
        cudaStreamCreateWithFlags(&s2, cudaStreamNonBlocking);
        cudaEventCreateWithFlags(&root, cudaEventDisableTiming);
        cudaEventCreateWithFlags(&done1, cudaEventDisableTiming);
        cudaEventCreateWithFlags(&done2, cudaEventDisableTiming);
    }
};
static HXStreams hx;

// ---------------- helpers ----------------
__device__ __forceinline__ uint32_t cvt_tf32(float f) {
    uint32_t o;
    asm("cvt.rna.tf32.f32 %0, %1;" : "=r"(o) : "f"(f));
    return o;
}

__device__ __forceinline__ void mma_tf32(float* c, const uint32_t* a, const uint32_t* b) {
    asm volatile(
        "mma.sync.aligned.m16n8k8.row.col.f32.tf32.tf32.f32 "
        "{%0,%1,%2,%3},{%4,%5,%6,%7},{%8,%9},{%0,%1,%2,%3};"
        : "+f"(c[0]), "+f"(c[1]), "+f"(c[2]), "+f"(c[3])
        : "r"(a[0]), "r"(a[1]), "r"(a[2]), "r"(a[3]), "r"(b[0]), "r"(b[1]));
}

__device__ __forceinline__ int load_idx(const void* raw, int e) {
    if (g_idx64) return (int)((const long long*)raw)[e];
    return ((const int*)raw)[e];
}

// ---------------- detect int32 vs int64 index dtype ----------------
__global__ void detect_kernel(const int* __restrict__ cur) {
    if (threadIdx.x == 0 && blockIdx.x == 0) {
        bool is64 = true;
        #pragma unroll
        for (int i = 0; i < 8; i++) {
            int lo = cur[2 * i];
            int hi = cur[2 * i + 1];
            if (lo < 0 || lo >= NN) is64 = false;
            if (hi != 0) is64 = false;
        }
        g_idx64 = is64 ? 1 : 0;
    }
}

// ---------------- zero bin counters ----------------
__global__ void zero_cnt_kernel() {
    int i = blockIdx.x * blockDim.x + threadIdx.x;
    if (i < NN) g_cnt[i] = 0;
}

// ---------------- histogram over targets ----------------
__global__ __launch_bounds__(256) void hist_kernel(const void* __restrict__ tgt, int E) {
    int e = blockIdx.x * blockDim.x + threadIdx.x;
    if (e < E) atomicAdd(&g_cnt[load_idx(tgt, e)], 1);
}

// ---------------- exclusive scan of 4096 counts (single block, shfl) -------
__global__ __launch_bounds__(256) void scan_kernel() {
    __shared__ int wsum[8];
    int tid = threadIdx.x, lane = tid & 31, warp = tid >> 5;
    int base = tid * 16;
    int4 v0 = reinterpret_cast<const int4*>(g_cnt)[tid * 4 + 0];
    int4 v1 = reinterpret_cast<const int4*>(g_cnt)[tid * 4 + 1];
    int4 v2 = reinterpret_cast<const int4*>(g_cnt)[tid * 4 + 2];
    int4 v3 = reinterpret_cast<const int4*>(g_cnt)[tid * 4 + 3];
    int c[16] = {v0.x, v0.y, v0.z, v0.w, v1.x, v1.y, v1.z, v1.w,
                 v2.x, v2.y, v2.z, v2.w, v3.x, v3.y, v3.z, v3.w};
    int local[16];
    int s = 0;
    #pragma unroll
    for (int j = 0; j < 16; j++) { local[j] = s; s += c[j]; }
    int v = s;
    #pragma unroll
    for (int o = 1; o < 32; o <<= 1) {
        int u = __shfl_up_sync(0xffffffffu, v, o);
        if (lane >= o) v += u;
    }
    if (lane == 31) wsum[warp] = v;
    __syncthreads();
    if (warp == 0) {
        int w = (lane < 8) ? wsum[lane] : 0;
        #pragma unroll
        for (int o = 1; o < 8; o <<= 1) {
            int u = __shfl_up_sync(0xffffffffu, w, o);
            if (lane >= o) w += u;
        }
        if (lane < 8) wsum[lane] = w;
    }
    __syncthreads();
    int excl = v - s + (warp ? wsum[warp - 1] : 0);
    #pragma unroll
    for (int j = 0; j < 16; j++) {
        int o = excl + local[j];
        g_off[base + j] = o;
        g_cur[base + j] = o;
    }
}

// ---------------- scatter edge ids into bins ----------------
__global__ __launch_bounds__(256) void scatter_kernel(
    const void* __restrict__ cur, const void* __restrict__ tgt, int E) {
    int e = blockIdx.x * blockDim.x + threadIdx.x;
    if (e < E) {
        int t = load_idx(tgt, e);
        int c = load_idx(cur, e);
        int pos = atomicAdd(&g_cur[t], 1);
        g_eid[pos] = e;
        g_ec[pos] = c;
    }
}

// ---------------- per-edge value pass (natural order, coalesced) -----------
__global__ __launch_bounds__(256) void val_kernel(
    const void* __restrict__ cur_raw, const void* __restrict__ tgt_raw,
    const float* __restrict__ act, const float* __restrict__ cases, int E) {
    int e = blockIdx.x * (blockDim.x >> 5) + (threadIdx.x >> 5);
    int lane = threadIdx.x & 31;
    if (e >= E) return;

    int c = load_idx(cur_raw, e);
    int t = load_idx(tgt_raw, e);

    float4 a = reinterpret_cast<const float4*>(act + (size_t)c * DD)[lane];
    float4 b = reinterpret_cast<const float4*>(act + (size_t)t * DD)[lane];
    float4 cc = reinterpret_cast<const float4*>(cases + (size_t)e * DD)[lane];

    float dx = a.x + cc.x - b.x;
    float dy = a.y + cc.y - b.y;
    float dz = a.z + cc.z - b.z;
    float dw = a.w + cc.w - b.w;
    float s = dx * dx + dy * dy + dz * dz + dw * dw;

    #pragma unroll
    for (int o = 16; o; o >>= 1) s += __shfl_xor_sync(0xffffffffu, s, o);

    if (lane == 0) g_val[e] = __expf(-sqrtf(s));
}

// ---------------- SpMM pass: one block per target row ----------------------
// out[t] = (sum_e val_e * feat[c_e]) / (norm_t + eps) + feat[t]
__global__ __launch_bounds__(256) void spmm_kernel(float* __restrict__ out) {
    __shared__ __align__(16) float s_acc[8][DD];
    __shared__ float s_nrm[8];
    int t = blockIdx.x;
    int tid = threadIdx.x, lane = tid & 31, warp = tid >> 5;

    float4 acc = make_float4(0.f, 0.f, 0.f, 0.f);
    float nrm = 0.f;

    int beg = g_off[t], cnt = g_cnt[t];
    for (int i = warp; i < cnt; i += 8) {
        int e = g_eid[beg + i];
        int c = g_ec[beg + i];
        float val = g_val[e];
        nrm += val;
        float4 f4 = reinterpret_cast<const float4*>(g_feat + (size_t)c * DD)[lane];
        acc.x += val * f4.x;
        acc.y += val * f4.y;
        acc.z += val * f4.z;
        acc.w += val * f4.w;
    }

    reinterpret_cast<float4*>(&s_acc[warp][0])[lane] = acc;
    if (lane == 0) s_nrm[warp] = nrm;
    __syncthreads();

    if (tid < DD) {
        float v = 0.f, nn = 0.f;
        #pragma unroll
        for (int w = 0; w < 8; w++) { v += s_acc[w][tid]; nn += s_nrm[w]; }
        float inv = 1.0f / (nn + EPSF);
        out[(size_t)t * DD + tid] = v * inv + g_feat[(size_t)t * DD + tid];
    }
}

// ---------------- tf32 tensor-core GEMM, split-K (known-good) --------------
__global__ __launch_bounds__(256) void mma_gemm_kernel(
    const float* __restrict__ A, const float* __restrict__ B) {
    __shared__ uint32_t As[BK * SA];
    __shared__ uint32_t Bs[BK * SB];

    int tid = threadIdx.x;
    int m0 = blockIdx.x * BM;
    int kb0 = blockIdx.y * KCHUNK;

    int lane = tid & 31, warp = tid >> 5;
    int wr = warp >> 1, wc = warp & 1;
    int g = lane >> 2, tc = lane & 3;
    int mbase = wr * 32, nbase = wc * 64;

    float acc[2][8][4];
    #pragma unroll
    for (int mi = 0; mi < 2; mi++)
        #pragma unroll
        for (int ni = 0; ni < 8; ni++)
            #pragma unroll
            for (int q = 0; q < 4; q++) acc[mi][ni][q] = 0.f;

    float4 ar[4], br[4];
    #pragma unroll
    for (int j = 0; j < 4; j++) {
        int id = tid + j * 256;
        ar[j] = *reinterpret_cast<const float4*>(
            A + (size_t)(m0 + (id >> 3)) * NN + kb0 + (id & 7) * 4);
        br[j] = *reinterpret_cast<const float4*>(
            B + (size_t)(kb0 + (id >> 5)) * DD + (id & 31) * 4);
    }

    for (int it = 0; it < NIT; it++) {
        #pragma unroll
        for (int j = 0; j < 4; j++) {
            int id = tid + j * 256;
            int r = id >> 3, c4 = id & 7;
            As[(c4 * 4 + 0) * SA + r] = cvt_tf32(ar[j].x);
            As[(c4 * 4 + 1) * SA + r] = cvt_tf32(ar[j].y);
            As[(c4 * 4 + 2) * SA + r] = cvt_tf32(ar[j].z);
            As[(c4 * 4 + 3) * SA + r] = cvt_tf32(ar[j].w);
            int rb = id >> 5, bc4 = id & 31;
            uint32_t* bp = &Bs[rb * SB + bc4 * 4];
            bp[0] = cvt_tf32(br[j].x);
            bp[1] = cvt_tf32(br[j].y);
            bp[2] = cvt_tf32(br[j].z);
            bp[3] = cvt_tf32(br[j].w);
        }
        __syncthreads();

        if (it + 1 < NIT) {
            int kb = kb0 + (it + 1) * BK;
            #pragma unroll
            for (int j = 0; j < 4; j++) {
                int id = tid + j * 256;
                ar[j] = *reinterpret_cast<const float4*>(
                    A + (size_t)(m0 + (id >> 3)) * NN + kb + (id & 7) * 4);
                br[j] = *reinterpret_cast<const float4*>(
                    B + (size_t)(kb + (id >> 5)) * DD + (id & 31) * 4);
            }
        }

        #pragma unroll
        for (int ks = 0; ks < 4; ks++) {
            int k0 = ks * 8;
            uint32_t a[2][4], b[8][2];
            const uint32_t* Ar0 = &As[(k0 + tc) * SA];
            const uint32_t* Ar1 = &As[(k0 + tc + 4) * SA];
            #pragma unroll
            for (int mi = 0; mi < 2; mi++) {
                int m = mbase + mi * 16 + g;
                a[mi][0] = Ar0[m];
                a[mi][1] = Ar0[m + 8];
                a[mi][2] = Ar1[m];
                a[mi][3] = Ar1[m + 8];
            }
            const uint32_t* Br0 = &Bs[(k0 + tc) * SB];
            const uint32_t* Br1 = &Bs[(k0 + tc + 4) * SB];
            #pragma unroll
            for (int ni = 0; ni < 8; ni++) {
                int n = nbase + ni * 8 + g;
                b[ni][0] = Br0[n];
                b[ni][1] = Br1[n];
            }
            #pragma unroll
            for (int mi = 0; mi < 2; mi++)
                #pragma unroll
                for (int ni = 0; ni < 8; ni++)
                    mma_tf32(acc[mi][ni], a[mi], b[ni]);
        }
        __syncthreads();
    }

    float* P = g_part[blockIdx.y];
    #pragma unroll
    for (int mi = 0; mi < 2; mi++) {
        #pragma unroll
        for (int ni = 0; ni < 8; ni++) {
            int r = m0 + mbase + mi * 16 + g;
            int cc = nbase + ni * 8 + tc * 2;
            *reinterpret_cast<float2*>(&P[(size_t)r * DD + cc]) =
                make_float2(acc[mi][ni][0], acc[mi][ni][1]);
            *reinterpret_cast<float2*>(&P[(size_t)(r + 8) * DD + cc]) =
                make_float2(acc[mi][ni][2], acc[mi][ni][3]);
        }
    }
}

// ---------------- split-K reduce: g_feat = sum(parts) ----------------
__global__ __launch_bounds__(256) void reduce_kernel() {
    int i = blockIdx.x * blockDim.x + threadIdx.x;
    float4 s = reinterpret_cast<const float4*>(g_part[0])[i];
    #pragma unroll
    for (int p = 1; p < SPLITK; p++) {
        float4 v = reinterpret_cast<const float4*>(g_part[p])[i];
        s.x += v.x; s.y += v.y; s.z += v.z; s.w += v.w;
    }
    reinterpret_cast<float4*>(g_feat)[i] = s;
}

// ---------------- launch ----------------
extern "C" void kernel_launch(void* const* d_in, const int* in_sizes, int n_in,
                              void* d_out, int out_size) {
    const void* cur = d_in[0];
    const void* tgt = d_in[1];
    const float* act = (const float*)d_in[2];
    const float* cases = (const float*)d_in[3];
    const float* W = (const float*)d_in[4];
    int E = in_sizes[0];
    float* out = (float*)d_out;

    int eb = (E + 255) / 256;
    int vb = (E + 7) / 8;
    dim3 ggrid(NN / BM, SPLITK);
    int rblocks = (NN * DD / 4) / 256;

    // root: index-dtype detect (needed by all branches)
    detect_kernel<<<1, 32>>>((const int*)cur);

    // fork
    cudaEventRecord(hx.root, 0);
    cudaStreamWaitEvent(hx.s1, hx.root, 0);
    cudaStreamWaitEvent(hx.s2, hx.root, 0);

    // branch s1: feature GEMM  (g_feat = W @ act)
    mma_gemm_kernel<<<ggrid, 256, 0, hx.s1>>>(W, act);
    reduce_kernel<<<rblocks, 256, 0, hx.s1>>>();
    cudaEventRecord(hx.done1, hx.s1);

    // branch s2: per-edge values (natural order)
    val_kernel<<<vb, 256, 0, hx.s2>>>(cur, tgt, act, cases, E);
    cudaEventRecord(hx.done2, hx.s2);

    // main branch: binning chain
    zero_cnt_kernel<<<16, 256>>>();
    hist_kernel<<<eb, 256>>>(tgt, E);
    scan_kernel<<<1, 256>>>();
    scatter_kernel<<<eb, 256>>>(cur, tgt, E);

    // join + final SpMM
    cudaStreamWaitEvent(0, hx.done1, 0);
    cudaStreamWaitEvent(0, hx.done2, 0);
    spmm_kernel<<<NN, 256>>>(out);
}

// round 9
// speedup vs baseline: 1.4818x; 1.4818x over previous
#include <cuda_runtime.h>
#include <math.h>
#include <stdint.h>

#define NN 4096
#define DD 128
#define EPSF 1e-12f
#define SPLITK 8
#define KCHUNK (NN / SPLITK)   // 512
#define BM 128
#define BK 32
#define NIT (KCHUNK / BK)      // 16
#define SA 132
#define SB 132

// ---------------- device scratch (no allocations allowed) ----------------
__device__ float g_feat[NN * DD];               // W @ activities
__device__ float g_part[SPLITK][NN * DD];       // split-K partials, 16 MB
__device__ float g_val[1 << 20];                // exp(-dist), stored in BIN order
__device__ float g_norm[NN];                    // row sums
__device__ int   g_cnt[NN];                     // edges per target
__device__ int   g_off[NN];                     // exclusive prefix
__device__ int   g_cur[NN];                     // scatter cursors
__device__ int   g_eid[1 << 20];                // permuted edge ids
__device__ int   g_ec[1 << 20];                 // permuted current ids
__device__ int   g_idx64;                       // 1 if indices are int64

// ---------------- streams/events for graph fork-join (no device mem) ------
struct HXStreams {
    cudaStream_t s1;
    cudaEvent_t root, done1;
    HXStreams() {
        cudaStreamCreateWithFlags(&s1, cudaStreamNonBlocking);
        cudaEventCreateWithFlags(&root, cudaEventDisableTiming);
        cudaEventCreateWithFlags(&done1, cudaEventDisableTiming);
    }
};
static HXStreams hx;

// ---------------- helpers ----------------
__device__ __forceinline__ uint32_t cvt_tf32(float f) {
    uint32_t o;
    asm("cvt.rna.tf32.f32 %0, %1;" : "=r"(o) : "f"(f));
    return o;
}

__device__ __forceinline__ void mma_tf32(float* c, const uint32_t* a, const uint32_t* b) {
    asm volatile(
        "mma.sync.aligned.m16n8k8.row.col.f32.tf32.tf32.f32 "
        "{%0,%1,%2,%3},{%4,%5,%6,%7},{%8,%9},{%0,%1,%2,%3};"
        : "+f"(c[0]), "+f"(c[1]), "+f"(c[2]), "+f"(c[3])
        : "r"(a[0]), "r"(a[1]), "r"(a[2]), "r"(a[3]), "r"(b[0]), "r"(b[1]));
}

__device__ __forceinline__ int load_idx(const void* raw, int e) {
    if (g_idx64) return (int)((const long long*)raw)[e];
    return ((const int*)raw)[e];
}

// ---------------- detect int32 vs int64 index dtype ----------------
__global__ void detect_kernel(const int* __restrict__ cur) {
    if (threadIdx.x == 0 && blockIdx.x == 0) {
        bool is64 = true;
        #pragma unroll
        for (int i = 0; i < 8; i++) {
            int lo = cur[2 * i];
            int hi = cur[2 * i + 1];
            if (lo < 0 || lo >= NN) is64 = false;
            if (hi != 0) is64 = false;
        }
        g_idx64 = is64 ? 1 : 0;
    }
}

// ---------------- zero bin counters ----------------
__global__ void zero_cnt_kernel() {
    int i = blockIdx.x * blockDim.x + threadIdx.x;
    if (i < NN) g_cnt[i] = 0;
}

// ---------------- histogram over targets ----------------
__global__ __launch_bounds__(256) void hist_kernel(const void* __restrict__ tgt, int E) {
    int e = blockIdx.x * blockDim.x + threadIdx.x;
    if (e < E) atomicAdd(&g_cnt[load_idx(tgt, e)], 1);
}

// ---------------- exclusive scan of 4096 counts (single block, shfl) -------
__global__ __launch_bounds__(256) void scan_kernel() {
    __shared__ int wsum[8];
    int tid = threadIdx.x, lane = tid & 31, warp = tid >> 5;
    int base = tid * 16;
    int4 v0 = reinterpret_cast<const int4*>(g_cnt)[tid * 4 + 0];
    int4 v1 = reinterpret_cast<const int4*>(g_cnt)[tid * 4 + 1];
    int4 v2 = reinterpret_cast<const int4*>(g_cnt)[tid * 4 + 2];
    int4 v3 = reinterpret_cast<const int4*>(g_cnt)[tid * 4 + 3];
    int c[16] = {v0.x, v0.y, v0.z, v0.w, v1.x, v1.y, v1.z, v1.w,
                 v2.x, v2.y, v2.z, v2.w, v3.x, v3.y, v3.z, v3.w};
    int local[16];
    int s = 0;
    #pragma unroll
    for (int j = 0; j < 16; j++) { local[j] = s; s += c[j]; }
    int v = s;
    #pragma unroll
    for (int o = 1; o < 32; o <<= 1) {
        int u = __shfl_up_sync(0xffffffffu, v, o);
        if (lane >= o) v += u;
    }
    if (lane == 31) wsum[warp] = v;
    __syncthreads();
    if (warp == 0) {
        int w = (lane < 8) ? wsum[lane] : 0;
        #pragma unroll
        for (int o = 1; o < 8; o <<= 1) {
            int u = __shfl_up_sync(0xffffffffu, w, o);
            if (lane >= o) w += u;
        }
        if (lane < 8) wsum[lane] = w;
    }
    __syncthreads();
    int excl = v - s + (warp ? wsum[warp - 1] : 0);
    #pragma unroll
    for (int j = 0; j < 16; j++) {
        int o = excl + local[j];
        g_off[base + j] = o;
        g_cur[base + j] = o;
    }
}

// ---------------- scatter edge ids into bins ----------------
__global__ __launch_bounds__(256) void scatter_kernel(
    const void* __restrict__ cur, const void* __restrict__ tgt, int E) {
    int e = blockIdx.x * blockDim.x + threadIdx.x;
    if (e < E) {
        int t = load_idx(tgt, e);
        int c = load_idx(cur, e);
        int pos = atomicAdd(&g_cur[t], 1);
        g_eid[pos] = e;
        g_ec[pos] = c;
    }
}

// ---------------- bin-ordered value pass: one block per target row ---------
// g_val[beg+i] = exp(-||act[c]+cases[e]-act[t]||), g_norm[t] = sum
__global__ __launch_bounds__(256) void val_bin_kernel(
    const float* __restrict__ act, const float* __restrict__ cases) {
    __shared__ float s_nrm[8];
    int t = blockIdx.x;
    int tid = threadIdx.x, lane = tid & 31, warp = tid >> 5;

    float4 t4 = reinterpret_cast<const float4*>(act + (size_t)t * DD)[lane];
    float nrm = 0.f;

    int beg = g_off[t], cnt = g_cnt[t];
    for (int i = warp; i < cnt; i += 8) {
        int e = g_eid[beg + i];
        int c = g_ec[beg + i];
        float4 c4 = reinterpret_cast<const float4*>(cases + (size_t)e * DD)[lane];
        float4 h4 = reinterpret_cast<const float4*>(act + (size_t)c * DD)[lane];
        float dx = h4.x + c4.x - t4.x;
        float dy = h4.y + c4.y - t4.y;
        float dz = h4.z + c4.z - t4.z;
        float dw = h4.w + c4.w - t4.w;
        float s = dx * dx + dy * dy + dz * dz + dw * dw;
        #pragma unroll
        for (int o = 16; o; o >>= 1) s += __shfl_xor_sync(0xffffffffu, s, o);
        float val = __expf(-sqrtf(s));
        nrm += val;
        if (lane == 0) g_val[beg + i] = val;   // bin-slot order (linear for consumer)
    }
    if (lane == 0) s_nrm[warp] = nrm;
    __syncthreads();
    if (warp == 0) {
        float x = (lane < 8) ? s_nrm[lane] : 0.f;
        #pragma unroll
        for (int o = 4; o; o >>= 1) x += __shfl_xor_sync(0xffffffffu, x, o);
        if (lane == 0) g_norm[t] = x;
    }
}

// ---------------- SpMM pass: one block per target row ----------------------
// out[t] = (sum_i val_i * feat[c_i]) / (norm_t + eps) + feat[t]
__global__ __launch_bounds__(256) void spmm_kernel(float* __restrict__ out) {
    __shared__ __align__(16) float s_acc[8][DD];
    int t = blockIdx.x;
    int tid = threadIdx.x, lane = tid & 31, warp = tid >> 5;

    float4 acc = make_float4(0.f, 0.f, 0.f, 0.f);

    int beg = g_off[t], cnt = g_cnt[t];
    for (int i = warp; i < cnt; i += 8) {
        float val = g_val[beg + i];            // broadcast (linear across warps)
        int c = g_ec[beg + i];
        float4 f4 = reinterpret_cast<const float4*>(g_feat + (size_t)c * DD)[lane];
        acc.x += val * f4.x;
        acc.y += val * f4.y;
        acc.z += val * f4.z;
        acc.w += val * f4.w;
    }

    reinterpret_cast<float4*>(&s_acc[warp][0])[lane] = acc;
    __syncthreads();

    if (tid < DD) {
        float v = 0.f;
        #pragma unroll
        for (int w = 0; w < 8; w++) v += s_acc[w][tid];
        float inv = 1.0f / (g_norm[t] + EPSF);
        out[(size_t)t * DD + tid] = v * inv + g_feat[(size_t)t * DD + tid];
    }
}

// ---------------- tf32 tensor-core GEMM, split-K (known-good) --------------
__global__ __launch_bounds__(256) void mma_gemm_kernel(
    const float* __restrict__ A, const float* __restrict__ B) {
    __shared__ uint32_t As[BK * SA];
    __shared__ uint32_t Bs[BK * SB];

    int tid = threadIdx.x;
    int m0 = blockIdx.x * BM;
    int kb0 = blockIdx.y * KCHUNK;

    int lane = tid & 31, warp = tid >> 5;
    int wr = warp >> 1, wc = warp & 1;
    int g = lane >> 2, tc = lane & 3;
    int mbase = wr * 32, nbase = wc * 64;

    float acc[2][8][4];
    #pragma unroll
    for (int mi = 0; mi < 2; mi++)
        #pragma unroll
        for (int ni = 0; ni < 8; ni++)
            #pragma unroll
            for (int q = 0; q < 4; q++) acc[mi][ni][q] = 0.f;

    float4 ar[4], br[4];
    #pragma unroll
    for (int j = 0; j < 4; j++) {
        int id = tid + j * 256;
        ar[j] = *reinterpret_cast<const float4*>(
            A + (size_t)(m0 + (id >> 3)) * NN + kb0 + (id & 7) * 4);
        br[j] = *reinterpret_cast<const float4*>(
            B + (size_t)(kb0 + (id >> 5)) * DD + (id & 31) * 4);
    }

    for (int it = 0; it < NIT; it++) {
        #pragma unroll
        for (int j = 0; j < 4; j++) {
            int id = tid + j * 256;
            int r = id >> 3, c4 = id & 7;
            As[(c4 * 4 + 0) * SA + r] = cvt_tf32(ar[j].x);
            As[(c4 * 4 + 1) * SA + r] = cvt_tf32(ar[j].y);
            As[(c4 * 4 + 2) * SA + r] = cvt_tf32(ar[j].z);
            As[(c4 * 4 + 3) * SA + r] = cvt_tf32(ar[j].w);
            int rb = id >> 5, bc4 = id & 31;
            uint32_t* bp = &Bs[rb * SB + bc4 * 4];
            bp[0] = cvt_tf32(br[j].x);
            bp[1] = cvt_tf32(br[j].y);
            bp[2] = cvt_tf32(br[j].z);
            bp[3] = cvt_tf32(br[j].w);
        }
        __syncthreads();

        if (it + 1 < NIT) {
            int kb = kb0 + (it + 1) * BK;
            #pragma unroll
            for (int j = 0; j < 4; j++) {
                int id = tid + j * 256;
                ar[j] = *reinterpret_cast<const float4*>(
                    A + (size_t)(m0 + (id >> 3)) * NN + kb + (id & 7) * 4);
                br[j] = *reinterpret_cast<const float4*>(
                    B + (size_t)(kb + (id >> 5)) * DD + (id & 31) * 4);
            }
        }

        #pragma unroll
        for (int ks = 0; ks < 4; ks++) {
            int k0 = ks * 8;
            uint32_t a[2][4], b[8][2];
            const uint32_t* Ar0 = &As[(k0 + tc) * SA];
            const uint32_t* Ar1 = &As[(k0 + tc + 4) * SA];
            #pragma unroll
            for (int mi = 0; mi < 2; mi++) {
                int m = mbase + mi * 16 + g;
                a[mi][0] = Ar0[m];
                a[mi][1] = Ar0[m + 8];
                a[mi][2] = Ar1[m];
                a[mi][3] = Ar1[m + 8];
            }
            const uint32_t* Br0 = &Bs[(k0 + tc) * SB];
            const uint32_t* Br1 = &Bs[(k0 + tc + 4) * SB];
            #pragma unroll
            for (int ni = 0; ni < 8; ni++) {
                int n = nbase + ni * 8 + g;
                b[ni][0] = Br0[n];
                b[ni][1] = Br1[n];
            }
            #pragma unroll
            for (int mi = 0; mi < 2; mi++)
                #pragma unroll
                for (int ni = 0; ni < 8; ni++)
                    mma_tf32(acc[mi][ni], a[mi], b[ni]);
        }
        __syncthreads();
    }

    float* P = g_part[blockIdx.y];
    #pragma unroll
    for (int mi = 0; mi < 2; mi++) {
        #pragma unroll
        for (int ni = 0; ni < 8; ni++) {
            int r = m0 + mbase + mi * 16 + g;
            int cc = nbase + ni * 8 + tc * 2;
            *reinterpret_cast<float2*>(&P[(size_t)r * DD + cc]) =
                make_float2(acc[mi][ni][0], acc[mi][ni][1]);
            *reinterpret_cast<float2*>(&P[(size_t)(r + 8) * DD + cc]) =
                make_float2(acc[mi][ni][2], acc[mi][ni][3]);
        }
    }
}

// ---------------- split-K reduce: g_feat = sum(parts) ----------------
__global__ __launch_bounds__(256) void reduce_kernel() {
    int i = blockIdx.x * blockDim.x + threadIdx.x;
    float4 s = reinterpret_cast<const float4*>(g_part[0])[i];
    #pragma unroll
    for (int p = 1; p < SPLITK; p++) {
        float4 v = reinterpret_cast<const float4*>(g_part[p])[i];
        s.x += v.x; s.y += v.y; s.z += v.z; s.w += v.w;
    }
    reinterpret_cast<float4*>(g_feat)[i] = s;
}

// ---------------- launch ----------------
extern "C" void kernel_launch(void* const* d_in, const int* in_sizes, int n_in,
                              void* d_out, int out_size) {
    const void* cur = d_in[0];
    const void* tgt = d_in[1];
    const float* act = (const float*)d_in[2];
    const float* cases = (const float*)d_in[3];
    const float* W = (const float*)d_in[4];
    int E = in_sizes[0];
    float* out = (float*)d_out;

    int eb = (E + 255) / 256;
    dim3 ggrid(NN / BM, SPLITK);
    int rblocks = (NN * DD / 4) / 256;

    // fork: GEMM branch (independent of everything else)
    cudaEventRecord(hx.root, 0);
    cudaStreamWaitEvent(hx.s1, hx.root, 0);
    mma_gemm_kernel<<<ggrid, 256, 0, hx.s1>>>(W, act);   // parts = W @ act
    reduce_kernel<<<rblocks, 256, 0, hx.s1>>>();         // g_feat = sum(parts)
    cudaEventRecord(hx.done1, hx.s1);

    // main branch: binning chain + bin-ordered edge values
    detect_kernel<<<1, 32>>>((const int*)cur);
    zero_cnt_kernel<<<16, 256>>>();
    hist_kernel<<<eb, 256>>>(tgt, E);
    scan_kernel<<<1, 256>>>();
    scatter_kernel<<<eb, 256>>>(cur, tgt, E);
    val_bin_kernel<<<NN, 256>>>(act, cases);

    // join + final SpMM
    cudaStreamWaitEvent(0, hx.done1, 0);
    spmm_kernel<<<NN, 256>>>(out);
}

// round 12
// speedup vs baseline: 1.4897x; 1.0053x over previous
#include <cuda_runtime.h>
#include <cuda_bf16.h>
#include <math.h>
#include <stdint.h>

#define NN 4096
#define DD 128
#define EPSF 1e-12f
#define SPLITK 8
#define KCHUNK (NN / SPLITK)   // 512
#define BM 128
#define BK 32
#define NIT (KCHUNK / BK)      // 16
#define SA 132
#define SB 132

// ---------------- device scratch (no allocations allowed) ----------------
__device__ float g_feat[NN * DD];               // W @ activities (fp32)
__device__ unsigned short g_featb[NN * DD];     // bf16 copy for gathers
__device__ unsigned short g_actb[NN * DD];      // bf16 copy of activities
__device__ float g_part[SPLITK][NN * DD];       // split-K partials, 16 MB
__device__ int   g_cnt[NN];                     // edges per target
__device__ int   g_off[NN];                     // exclusive prefix
__device__ int   g_cur[NN];                     // scatter cursors
__device__ int   g_eid[1 << 20];                // permuted edge ids
__device__ int   g_ec[1 << 20];                 // permuted current ids
__device__ int   g_idx64;                       // 1 if indices are int64

// ---------------- helpers ----------------
__device__ __forceinline__ uint32_t cvt_tf32(float f) {
    uint32_t o;
    asm("cvt.rna.tf32.f32 %0, %1;" : "=r"(o) : "f"(f));
    return o;
}

__device__ __forceinline__ void mma_tf32(float* c, const uint32_t* a, const uint32_t* b) {
    asm volatile(
        "mma.sync.aligned.m16n8k8.row.col.f32.tf32.tf32.f32 "
        "{%0,%1,%2,%3},{%4,%5,%6,%7},{%8,%9},{%0,%1,%2,%3};"
        : "+f"(c[0]), "+f"(c[1]), "+f"(c[2]), "+f"(c[3])
        : "r"(a[0]), "r"(a[1]), "r"(a[2]), "r"(a[3]), "r"(b[0]), "r"(b[1]));
}

__device__ __forceinline__ int load_idx(const void* raw, int e) {
    if (g_idx64) return (int)((const long long*)raw)[e];
    return ((const int*)raw)[e];
}

// unpack 4 bf16 packed in a uint2 into 4 floats
__device__ __forceinline__ float4 bf4_to_f4(uint2 v) {
    __nv_bfloat162 p0 = *reinterpret_cast<__nv_bfloat162*>(&v.x);
    __nv_bfloat162 p1 = *reinterpret_cast<__nv_bfloat162*>(&v.y);
    float4 r;
    r.x = __low2float(p0);
    r.y = __high2float(p0);
    r.z = __low2float(p1);
    r.w = __high2float(p1);
    return r;
}

// ---------------- detect int32 vs int64 index dtype ----------------
__global__ void detect_kernel(const int* __restrict__ cur) {
    if (threadIdx.x == 0 && blockIdx.x == 0) {
        bool is64 = true;
        #pragma unroll
        for (int i = 0; i < 8; i++) {
            int lo = cur[2 * i];
            int hi = cur[2 * i + 1];
            if (lo < 0 || lo >= NN) is64 = false;
            if (hi != 0) is64 = false;
        }
        g_idx64 = is64 ? 1 : 0;
    }
}

// ---------------- zero bin counters ----------------
__global__ void zero_cnt_kernel() {
    int i = blockIdx.x * blockDim.x + threadIdx.x;
    if (i < NN) g_cnt[i] = 0;
}

// ---------------- act -> bf16 shadow copy ----------------
__global__ __launch_bounds__(256) void cvt_act_kernel(const float* __restrict__ act) {
    int i = blockIdx.x * blockDim.x + threadIdx.x;   // NN*DD total
    g_actb[i] = __bfloat16_as_ushort(__float2bfloat16(act[i]));
}

// ---------------- histogram over targets ----------------
__global__ __launch_bounds__(256) void hist_kernel(const void* __restrict__ tgt, int E) {
    int e = blockIdx.x * blockDim.x + threadIdx.x;
    if (e < E) atomicAdd(&g_cnt[load_idx(tgt, e)], 1);
}

// ---------------- exclusive scan of 4096 counts (single block, shfl) -------
__global__ __launch_bounds__(256) void scan_kernel() {
    __shared__ int wsum[8];
    int tid = threadIdx.x, lane = tid & 31, warp = tid >> 5;
    int base = tid * 16;
    int4 v0 = reinterpret_cast<const int4*>(g_cnt)[tid * 4 + 0];
    int4 v1 = reinterpret_cast<const int4*>(g_cnt)[tid * 4 + 1];
    int4 v2 = reinterpret_cast<const int4*>(g_cnt)[tid * 4 + 2];
    int4 v3 = reinterpret_cast<const int4*>(g_cnt)[tid * 4 + 3];
    int c[16] = {v0.x, v0.y, v0.z, v0.w, v1.x, v1.y, v1.z, v1.w,
                 v2.x, v2.y, v2.z, v2.w, v3.x, v3.y, v3.z, v3.w};
    int local[16];
    int s = 0;
    #pragma unroll
    for (int j = 0; j < 16; j++) { local[j] = s; s += c[j]; }
    int v = s;
    #pragma unroll
    for (int o = 1; o < 32; o <<= 1) {
        int u = __shfl_up_sync(0xffffffffu, v, o);
        if (lane >= o) v += u;
    }
    if (lane == 31) wsum[warp] = v;
    __syncthreads();
    if (warp == 0) {
        int w = (lane < 8) ? wsum[lane] : 0;
        #pragma unroll
        for (int o = 1; o < 8; o <<= 1) {
            int u = __shfl_up_sync(0xffffffffu, w, o);
            if (lane >= o) w += u;
        }
        if (lane < 8) wsum[lane] = w;
    }
    __syncthreads();
    int excl = v - s + (warp ? wsum[warp - 1] : 0);
    #pragma unroll
    for (int j = 0; j < 16; j++) {
        int o = excl + local[j];
        g_off[base + j] = o;
        g_cur[base + j] = o;
    }
}

// ---------------- scatter edge ids into bins ----------------
__global__ __launch_bounds__(256) void scatter_kernel(
    const void* __restrict__ cur, const void* __restrict__ tgt, int E) {
    int e = blockIdx.x * blockDim.x + threadIdx.x;
    if (e < E) {
        int t = load_idx(tgt, e);
        int c = load_idx(cur, e);
        int pos = atomicAdd(&g_cur[t], 1);
        g_eid[pos] = e;
        g_ec[pos] = c;
    }
}

// ---------------- fused edge + SpMM pass: one block per target row ---------
// out[t] = (sum_e val_e * feat[c_e]) / (norm_t + eps) + feat[t]
// act[c] and feat[c] gathered as bf16 (half the L2 bytes).
__global__ __launch_bounds__(256) void fused_edge_kernel(
    const float* __restrict__ act, const float* __restrict__ cases,
    float* __restrict__ out) {
    __shared__ __align__(16) float s_acc[8][DD];   // per-warp accumulators
    __shared__ float s_nrm[8];
    int t = blockIdx.x;
    int tid = threadIdx.x, lane = tid & 31, warp = tid >> 5;

    // target row in fp32 registers (loaded once per block)
    float4 t4 = reinterpret_cast<const float4*>(act + (size_t)t * DD)[lane];
    float4 acc = make_float4(0.f, 0.f, 0.f, 0.f);
    float nrm = 0.f;

    int beg = g_off[t], cnt = g_cnt[t];
    for (int i = warp; i < cnt; i += 8) {
        int e = g_eid[beg + i];
        int c = g_ec[beg + i];
        float4 c4 = reinterpret_cast<const float4*>(cases + (size_t)e * DD)[lane];
        uint2 hb = reinterpret_cast<const uint2*>(g_actb + (size_t)c * DD)[lane];
        float4 h4 = bf4_to_f4(hb);
        float dx = h4.x + c4.x - t4.x;
        float dy = h4.y + c4.y - t4.y;
        float dz = h4.z + c4.z - t4.z;
        float dw = h4.w + c4.w - t4.w;
        float s = dx * dx + dy * dy + dz * dz + dw * dw;
        #pragma unroll
        for (int o = 16; o; o >>= 1) s += __shfl_xor_sync(0xffffffffu, s, o);
        float val = __expf(-sqrtf(s));    // same value in all lanes
        nrm += val;
        uint2 fb = reinterpret_cast<const uint2*>(g_featb + (size_t)c * DD)[lane];
        float4 f4 = bf4_to_f4(fb);
        acc.x += val * f4.x;
        acc.y += val * f4.y;
        acc.z += val * f4.z;
        acc.w += val * f4.w;
    }

    reinterpret_cast<float4*>(&s_acc[warp][0])[lane] = acc;
    if (lane == 0) s_nrm[warp] = nrm;
    __syncthreads();

    if (tid < DD) {
        float v = 0.f, nn = 0.f;
        #pragma unroll
        for (int w = 0; w < 8; w++) { v += s_acc[w][tid]; nn += s_nrm[w]; }
        float inv = 1.0f / (nn + EPSF);
        out[(size_t)t * DD + tid] = v * inv + g_feat[(size_t)t * DD + tid];
    }
}

// ---------------- tf32 tensor-core GEMM, split-K (known-good) --------------
// parts[split] = W[4096, KCHUNK] * act[KCHUNK, 128]
__global__ __launch_bounds__(256) void mma_gemm_kernel(
    const float* __restrict__ A, const float* __restrict__ B) {
    __shared__ uint32_t As[BK * SA];
    __shared__ uint32_t Bs[BK * SB];

    int tid = threadIdx.x;
    int m0 = blockIdx.x * BM;
    int kb0 = blockIdx.y * KCHUNK;

    int lane = tid & 31, warp = tid >> 5;
    int wr = warp >> 1, wc = warp & 1;
    int g = lane >> 2, tc = lane & 3;
    int mbase = wr * 32, nbase = wc * 64;

    float acc[2][8][4];
    #pragma unroll
    for (int mi = 0; mi < 2; mi++)
        #pragma unroll
        for (int ni = 0; ni < 8; ni++)
            #pragma unroll
            for (int q = 0; q < 4; q++) acc[mi][ni][q] = 0.f;

    float4 ar[4], br[4];
    #pragma unroll
    for (int j = 0; j < 4; j++) {
        int id = tid + j * 256;
        ar[j] = *reinterpret_cast<const float4*>(
            A + (size_t)(m0 + (id >> 3)) * NN + kb0 + (id & 7) * 4);
        br[j] = *reinterpret_cast<const float4*>(
            B + (size_t)(kb0 + (id >> 5)) * DD + (id & 31) * 4);
    }

    for (int it = 0; it < NIT; it++) {
        #pragma unroll
        for (int j = 0; j < 4; j++) {
            int id = tid + j * 256;
            int r = id >> 3, c4 = id & 7;
            As[(c4 * 4 + 0) * SA + r] = cvt_tf32(ar[j].x);
            As[(c4 * 4 + 1) * SA + r] = cvt_tf32(ar[j].y);
            As[(c4 * 4 + 2) * SA + r] = cvt_tf32(ar[j].z);
            As[(c4 * 4 + 3) * SA + r] = cvt_tf32(ar[j].w);
            int rb = id >> 5, bc4 = id & 31;
            uint32_t* bp = &Bs[rb * SB + bc4 * 4];
            bp[0] = cvt_tf32(br[j].x);
            bp[1] = cvt_tf32(br[j].y);
            bp[2] = cvt_tf32(br[j].z);
            bp[3] = cvt_tf32(br[j].w);
        }
        __syncthreads();

        if (it + 1 < NIT) {
            int kb = kb0 + (it + 1) * BK;
            #pragma unroll
            for (int j = 0; j < 4; j++) {
                int id = tid + j * 256;
                ar[j] = *reinterpret_cast<const float4*>(
                    A + (size_t)(m0 + (id >> 3)) * NN + kb + (id & 7) * 4);
                br[j] = *reinterpret_cast<const float4*>(
                    B + (size_t)(kb + (id >> 5)) * DD + (id & 31) * 4);
            }
        }

        #pragma unroll
        for (int ks = 0; ks < 4; ks++) {
            int k0 = ks * 8;
            uint32_t a[2][4], b[8][2];
            const uint32_t* Ar0 = &As[(k0 + tc) * SA];
            const uint32_t* Ar1 = &As[(k0 + tc + 4) * SA];
            #pragma unroll
            for (int mi = 0; mi < 2; mi++) {
                int m = mbase + mi * 16 + g;
                a[mi][0] = Ar0[m];
                a[mi][1] = Ar0[m + 8];
                a[mi][2] = Ar1[m];
                a[mi][3] = Ar1[m + 8];
            }
            const uint32_t* Br0 = &Bs[(k0 + tc) * SB];
            const uint32_t* Br1 = &Bs[(k0 + tc + 4) * SB];
            #pragma unroll
            for (int ni = 0; ni < 8; ni++) {
                int n = nbase + ni * 8 + g;
                b[ni][0] = Br0[n];
                b[ni][1] = Br1[n];
            }
            #pragma unroll
            for (int mi = 0; mi < 2; mi++)
                #pragma unroll
                for (int ni = 0; ni < 8; ni++)
                    mma_tf32(acc[mi][ni], a[mi], b[ni]);
        }
        __syncthreads();
    }

    float* P = g_part[blockIdx.y];
    #pragma unroll
    for (int mi = 0; mi < 2; mi++) {
        #pragma unroll
        for (int ni = 0; ni < 8; ni++) {
            int r = m0 + mbase + mi * 16 + g;
            int cc = nbase + ni * 8 + tc * 2;
            *reinterpret_cast<float2*>(&P[(size_t)r * DD + cc]) =
                make_float2(acc[mi][ni][0], acc[mi][ni][1]);
            *reinterpret_cast<float2*>(&P[(size_t)(r + 8) * DD + cc]) =
                make_float2(acc[mi][ni][2], acc[mi][ni][3]);
        }
    }
}

// ---------------- split-K reduce: g_feat (fp32) + g_featb (bf16) ----------
__global__ __launch_bounds__(256) void reduce_kernel() {
    int i = blockIdx.x * blockDim.x + threadIdx.x;   // float4 index
    float4 s = reinterpret_cast<const float4*>(g_part[0])[i];
    #pragma unroll
    for (int p = 1; p < SPLITK; p++) {
        float4 v = reinterpret_cast<const float4*>(g_part[p])[i];
        s.x += v.x; s.y += v.y; s.z += v.z; s.w += v.w;
    }
    reinterpret_cast<float4*>(g_feat)[i] = s;
    // packed bf16 copy (4 values -> uint2)
    __nv_bfloat162 p0 = __floats2bfloat162_rn(s.x, s.y);
    __nv_bfloat162 p1 = __floats2bfloat162_rn(s.z, s.w);
    uint2 pk;
    pk.x = *reinterpret_cast<uint32_t*>(&p0);
    pk.y = *reinterpret_cast<uint32_t*>(&p1);
    reinterpret_cast<uint2*>(g_featb)[i] = pk;
}

// ---------------- launch ----------------
extern "C" void kernel_launch(void* const* d_in, const int* in_sizes, int n_in,
                              void* d_out, int out_size) {
    const void* cur = d_in[0];
    const void* tgt = d_in[1];
    const float* act = (const float*)d_in[2];
    const float* cases = (const float*)d_in[3];
    const float* W = (const float*)d_in[4];
    int E = in_sizes[0];
    float* out = (float*)d_out;

    int eb = (E + 255) / 256;
    int rblocks = (NN * DD / 4) / 256;
    int cblocks = (NN * DD) / 256;
    dim3 ggrid(NN / BM, SPLITK);

    detect_kernel<<<1, 32>>>((const int*)cur);
    zero_cnt_kernel<<<16, 256>>>();
    cvt_act_kernel<<<cblocks, 256>>>(act);        // g_actb = bf16(act)

    hist_kernel<<<eb, 256>>>(tgt, E);
    scan_kernel<<<1, 256>>>();
    scatter_kernel<<<eb, 256>>>(cur, tgt, E);

    mma_gemm_kernel<<<ggrid, 256>>>(W, act);      // parts = W @ act
    reduce_kernel<<<rblocks, 256>>>();            // g_feat + g_featb

    fused_edge_kernel<<<NN, 256>>>(act, cases, out);
}